// round 10
// baseline (speedup 1.0000x reference)
#include <cuda_runtime.h>

#define N_PRED 20
#define N_LAB  12
#define QTR    5     // preds per thread (4 threads per row)

typedef unsigned long long u64;

__device__ __forceinline__ float sqrt_approx(float x){ float r; asm("sqrt.approx.f32 %0,%1;":"=f"(r):"f"(x)); return r; }
__device__ __forceinline__ float log2_approx(float x){ float r; asm("lg2.approx.f32 %0,%1;":"=f"(r):"f"(x)); return r; }
__device__ __forceinline__ u64 pk2(float a, float b){ u64 r; asm("mov.b64 %0,{%1,%2};":"=l"(r):"f"(a),"f"(b)); return r; }
__device__ __forceinline__ void upk2(u64 v, float&a, float&b){ asm("mov.b64 {%0,%1},%2;":"=f"(a),"=f"(b):"l"(v)); }
__device__ __forceinline__ u64 add2(u64 a,u64 b){ u64 r; asm("add.rn.f32x2 %0,%1,%2;":"=l"(r):"l"(a),"l"(b)); return r; }
__device__ __forceinline__ u64 mul2(u64 a,u64 b){ u64 r; asm("mul.rn.f32x2 %0,%1,%2;":"=l"(r):"l"(a),"l"(b)); return r; }
__device__ __forceinline__ u64 fma2(u64 a,u64 b,u64 c){ u64 r; asm("fma.rn.f32x2 %0,%1,%2,%3;":"=l"(r):"l"(a),"l"(b),"l"(c)); return r; }

__global__ __launch_bounds__(256, 5)
void myloss_kernel(const float4* __restrict__ pred,   // [B, 20, 4]
                   const float4* __restrict__ label,  // [B, 12, 4]
                   float* __restrict__ out, int B)
{
    int t = blockIdx.x * blockDim.x + threadIdx.x;
    int b = t >> 2;          // row
    int h = t & 3;           // quarter of the preds owned by this thread
    bool valid = (b < B);
    if (!valid) b = B - 1;   // keep warps converged for the shuffles

    // My 5 preds. x/y of preds 0-3 stored NEGATED in f32x2 pairs (packed adds
    // implement the subtractions); pred 4 and everything else stays scalar.
    float pz[QTR], pw[QTR];
    u64 nx01, nx23, ny01, ny23;
    float px4, py4;
    const float4* pr = pred + (long)b * N_PRED + h * QTR;
    {
        float4 v0 = pr[0], v1 = pr[1], v2 = pr[2], v3 = pr[3], v4 = pr[4];
        nx01 = pk2(-v0.x, -v1.x);  nx23 = pk2(-v2.x, -v3.x);
        ny01 = pk2(-v0.y, -v1.y);  ny23 = pk2(-v2.y, -v3.y);
        px4 = v4.x; py4 = v4.y;
        pz[0]=v0.z; pz[1]=v1.z; pz[2]=v2.z; pz[3]=v3.z; pz[4]=v4.z;
        pw[0]=v0.w; pw[1]=v1.w; pw[2]=v2.w; pw[3]=v3.w; pw[4]=v4.w;
    }

    const float4* lb = label + (long)b * N_LAB;
    float csum = 0.f;          // sum of winning keys (cost + <=31ulp idx noise)
    unsigned cnt = 0u;         // 4-bit match multiplicity per local pred (5 nibbles)
    const int gbase = QTR * h; // my first global pred index

    #pragma unroll
    for (int l = 0; l < N_LAB; l++) {
        float4 y = lb[l];      // 4 lanes share the sector -> L1 broadcast
        u64 yx2 = pk2(y.x, y.x), yy2 = pk2(y.y, y.y);

        // Packed quadratic part for preds 0-3 (8 ops instead of 16).
        u64 dx01 = add2(yx2, nx01), dx23 = add2(yx2, nx23);
        u64 dy01 = add2(yy2, ny01), dy23 = add2(yy2, ny23);
        u64 d01  = fma2(dx01, dx01, mul2(dy01, dy01));
        u64 d23  = fma2(dx23, dx23, mul2(dy23, dy23));
        float d0, d1, d2, d3;  upk2(d01, d0, d1);  upk2(d23, d2, d3);
        float dx4 = y.x - px4, dy4 = y.y - py4;
        float d4  = fmaf(dx4, dx4, dy4 * dy4);

        // Scalar tail: sqrt + |dz| + key embed (low 5 mantissa bits = GLOBAL
        // pred index -> nonneg float min == lexicographic (cost, idx) min ==
        // jnp.argmin first-min tie-break across all 20 preds).
        float dsq[QTR] = {d0, d1, d2, d3, d4};
        float m[QTR];
        #pragma unroll
        for (int j = 0; j < QTR; j++) {
            float c = sqrt_approx(dsq[j]) + fabsf(y.z - pz[j]);
            m[j] = __uint_as_float((__float_as_uint(c) & 0xFFFFFFE0u) | (unsigned)(gbase + j));
        }
        float w  = fminf(fminf(fminf(m[0], m[1]), fminf(m[2], m[3])), m[4]);

        // 2-round butterfly merge across the 4 lanes of this row.
        float w1 = fminf(w,  __shfl_xor_sync(0xffffffffu, w,  1));
        float wc = fminf(w1, __shfl_xor_sync(0xffffffffu, w1, 2));

        csum += wc;            // idx bits add ~2e-6 relative noise (verified ok)
        if (__float_as_uint(wc) == __float_as_uint(w)) {      // unique keys:
            int j = (int)(__float_as_uint(w) & 31u) - gbase;  // exactly one lane
            cnt += 1u << (4 * j);
        }
    }

    // Epilogue: exactly one log per pred.
    //   matched (n>0): -n*log(pw+eps)/12
    //   unmatched:     (-log(1-pw+eps) + 0.5*pz)*0.5/8
    const float EPS = 1e-6f;
    const float LN2 = 0.69314718055994530942f;
    float S = 0.f;
    #pragma unroll
    for (int j = 0; j < QTR; j++) {
        int n = (int)((cnt >> (4 * j)) & 15u);
        bool mt = (n > 0);
        float arg  = mt ? (pw[j] + EPS) : ((1.0f + EPS) - pw[j]);
        float lg   = log2_approx(arg);
        float coef = mt ? ((float)n) * (-LN2 / 12.0f) : (-LN2 / 16.0f);
        S = fmaf(coef, lg, S);
        if (!mt) S = fmaf(pz[j], 1.0f / 32.0f, S);
    }
    S += __shfl_xor_sync(0xffffffffu, S, 1);
    S += __shfl_xor_sync(0xffffffffu, S, 2);

    if (valid && h == 0)
        out[b] = fmaf(csum, 0.5f / 12.0f, S);
}

extern "C" void kernel_launch(void* const* d_in, const int* in_sizes, int n_in,
                              void* d_out, int out_size)
{
    const float4* pred  = (const float4*)d_in[0];
    const float4* label = (const float4*)d_in[1];
    float* out = (float*)d_out;
    int B = in_sizes[0] / (N_PRED * 4);

    long threads_total = 4L * B;
    int threads = 256;
    int blocks = (int)((threads_total + threads - 1) / threads);
    myloss_kernel<<<blocks, threads>>>(pred, label, out, B);
}